// round 4
// baseline (speedup 1.0000x reference)
#include <cuda_runtime.h>
#include <cuda_bf16.h>
#include <math.h>

#define N_NODES 50000
#define N_EDGES 800000
#define IN_FEATS 128
#define HIDDEN 32
#define HEADS 4
#define FEAT 128           // HEADS*HIDDEN
#define N_GRAPHS 64
#define NEG_SLOPE 0.2f

// ---------------- scratch (static device globals; no allocation) ----------------
__device__ float g_feat[(size_t)N_NODES * FEAT];   // feat of current layer (W-projected)
__device__ float g_h[(size_t)N_NODES * FEAT];      // layer output / next layer input
__device__ float g_el[N_NODES * HEADS];
__device__ float g_er[N_NODES * HEADS];
__device__ int   g_deg[N_NODES];
__device__ int   g_cur[N_NODES];
__device__ int   g_off[N_NODES + 1];
__device__ int   g_srcsorted[N_EDGES];
__device__ unsigned g_pool[N_GRAPHS * FEAT];

// TF32 rounding (matches JAX/XLA default f32 matmul precision on GPU)
__device__ __forceinline__ float tf32r(float x) {
    unsigned u;
    asm("cvt.rna.tf32.f32 %0, %1;" : "=r"(u) : "f"(x));
    return __uint_as_float(u);
}

// order-preserving float <-> uint encode for atomicMax
__device__ __forceinline__ unsigned fenc(float f) {
    unsigned u = __float_as_uint(f);
    return (u & 0x80000000u) ? ~u : (u | 0x80000000u);
}
__device__ __forceinline__ float fdec(unsigned k) {
    return (k & 0x80000000u) ? __uint_as_float(k ^ 0x80000000u) : __uint_as_float(~k);
}
#define ENC_NEG_INF 0x007FFFFFu   // fenc(-inf)

// ---------------- init: zero deg/cur, pool = -inf ----------------
__global__ void init_kernel() {
    int i = blockIdx.x * blockDim.x + threadIdx.x;
    if (i < N_NODES) { g_deg[i] = 0; g_cur[i] = 0; }
    if (i < N_GRAPHS * FEAT) g_pool[i] = ENC_NEG_INF;
}

// ---------------- CSR build ----------------
__global__ void deg_kernel(const int* __restrict__ dst) {
    int i = blockIdx.x * blockDim.x + threadIdx.x;
    if (i < N_EDGES) atomicAdd(&g_deg[dst[i]], 1);
}

__global__ void scan_kernel() {
    __shared__ int sh[1024];
    __shared__ int carry;
    if (threadIdx.x == 0) carry = 0;
    __syncthreads();
    for (int base = 0; base < N_NODES; base += 1024) {
        int i = base + threadIdx.x;
        int v = (i < N_NODES) ? g_deg[i] : 0;
        sh[threadIdx.x] = v;
        __syncthreads();
        for (int st = 1; st < 1024; st <<= 1) {
            int t = (threadIdx.x >= st) ? sh[threadIdx.x - st] : 0;
            __syncthreads();
            sh[threadIdx.x] += t;
            __syncthreads();
        }
        if (i < N_NODES) g_off[i] = carry + sh[threadIdx.x] - v;  // exclusive
        __syncthreads();
        if (threadIdx.x == 1023) carry += sh[1023];
        __syncthreads();
    }
    if (threadIdx.x == 0) g_off[N_NODES] = carry;
}

__global__ void scatter_kernel(const int* __restrict__ src, const int* __restrict__ dst) {
    int i = blockIdx.x * blockDim.x + threadIdx.x;
    if (i < N_EDGES) {
        int d = dst[i];
        int pos = g_off[d] + atomicAdd(&g_cur[d], 1);
        g_srcsorted[pos] = src[i];
    }
}

// ---------------- fused GEMM + el/er ----------------
// feat = X[ids] @ W (layer 0: gather from X via ids) or g_h @ W (layer 1: X==null).
// Operands rounded to TF32 to match the reference's XLA matmul precision.
// Then el[n][h] = sum_d feat[n][h][d]*al[h][d], er likewise (warp shuffle reduce).
#define GEMM_ROWS 32
#define GEMM_THREADS 256
#define GEMM_SMEM ((128*128 + GEMM_ROWS*128 + 256) * 4)

__global__ void gemm_kernel(const float* __restrict__ X, const int* __restrict__ ids,
                            const float* __restrict__ W, const float* __restrict__ al,
                            const float* __restrict__ ar) {
    extern __shared__ float sh[];
    float* Ws  = sh;                       // 128*128
    float* Hs  = Ws + 128 * 128;           // 32*128
    float* als = Hs + GEMM_ROWS * 128;     // 128
    float* ars = als + 128;                // 128

    int t = threadIdx.x;
    for (int i = t; i < 128 * 128 / 4; i += GEMM_THREADS) {
        float4 w4 = ((const float4*)W)[i];
        w4.x = tf32r(w4.x); w4.y = tf32r(w4.y);
        w4.z = tf32r(w4.z); w4.w = tf32r(w4.w);
        ((float4*)Ws)[i] = w4;
    }
    if (t < 128) { als[t] = al[t]; ars[t] = ar[t]; }

    int row0 = blockIdx.x * GEMM_ROWS;
    for (int i = t; i < GEMM_ROWS * 128 / 4; i += GEMM_THREADS) {
        int r = i >> 5;           // 32 float4 per 128-float row
        int c4 = i & 31;
        int node = row0 + r;
        if (node < N_NODES) {
            float4 h4;
            if (X) {
                int srow = ids ? ids[node] : node;
                h4 = ((const float4*)(X + (size_t)srow * 128))[c4];
            } else {
                h4 = ((const float4*)(g_h + (size_t)node * 128))[c4];
            }
            h4.x = tf32r(h4.x); h4.y = tf32r(h4.y);
            h4.z = tf32r(h4.z); h4.w = tf32r(h4.w);
            ((float4*)Hs)[i] = h4;
        }
    }
    __syncthreads();

    int j  = t & 127;     // output column (= h*32 + d)
    int r0 = t >> 7;      // row parity
    float acc[16];
#pragma unroll
    for (int i = 0; i < 16; i++) acc[i] = 0.f;

    for (int k = 0; k < 128; k++) {
        float w = Ws[k * 128 + j];
#pragma unroll
        for (int i = 0; i < 16; i++)
            acc[i] += Hs[(i * 2 + r0) * 128 + k] * w;
    }

    int h = j >> 5;
    int lane = t & 31;
    float alv = als[j], arv = ars[j];
#pragma unroll
    for (int i = 0; i < 16; i++) {
        int node = row0 + i * 2 + r0;
        if (node < N_NODES) {
            float v = acc[i];
            g_feat[(size_t)node * FEAT + j] = v;
            float a = v * alv, b = v * arv;
#pragma unroll
            for (int s = 16; s > 0; s >>= 1) {
                a += __shfl_xor_sync(0xffffffffu, a, s);
                b += __shfl_xor_sync(0xffffffffu, b, s);
            }
            if (lane == 0) {
                g_el[node * HEADS + h] = a;
                g_er[node * HEADS + h] = b;
            }
        }
    }
}

// ---------------- edge aggregation: one warp per dst node, online softmax ----------------
__global__ void edge_agg_kernel() {
    int gw = (blockIdx.x * blockDim.x + threadIdx.x) >> 5;
    int lane = threadIdx.x & 31;
    if (gw >= N_NODES) return;
    int n = gw;

    float4 er4 = *(const float4*)&g_er[n * HEADS];
    float er[4] = {er4.x, er4.y, er4.z, er4.w};
    float m[4], den[4], acc[4];
#pragma unroll
    for (int h = 0; h < 4; h++) { m[h] = -INFINITY; den[h] = 0.f; acc[h] = 0.f; }

    int s = g_off[n], e = g_off[n + 1];
    for (int i = s; i < e; i++) {
        int src = g_srcsorted[i];
        const float* f = g_feat + (size_t)src * FEAT;
        float4 el4 = *(const float4*)&g_el[src * HEADS];
        float el[4] = {el4.x, el4.y, el4.z, el4.w};
#pragma unroll
        for (int h = 0; h < 4; h++) {
            float x = el[h] + er[h];
            x = (x > 0.f) ? x : NEG_SLOPE * x;
            float fv = f[h * 32 + lane];
            if (x <= m[h]) {
                float p = __expf(x - m[h]);
                den[h] += p;
                acc[h] += p * fv;
            } else {
                float sc = __expf(m[h] - x);     // = 0 when m = -inf
                den[h] = den[h] * sc + 1.f;
                acc[h] = acc[h] * sc + fv;
                m[h] = x;
            }
        }
    }
#pragma unroll
    for (int h = 0; h < 4; h++) {
        float o = acc[h] / (den[h] + 1e-10f);
        o = (o > 0.f) ? o : expm1f(o);           // elu
        g_h[(size_t)n * FEAT + h * 32 + lane] = o;
    }
}

// ---------------- per-graph max pool (node_graph_id sorted -> run-length local max) ----------------
#define POOL_CHUNK 128
__global__ void pool_kernel(const int* __restrict__ gid) {
    int f = threadIdx.x;   // 128 threads = feature dims
    int n0 = blockIdx.x * POOL_CHUNK;
    int n1 = n0 + POOL_CHUNK; if (n1 > N_NODES) n1 = N_NODES;
    int cur = -1;
    unsigned best = 0;
    for (int n = n0; n < n1; n++) {
        int g = gid[n];                               // broadcast load
        unsigned enc = fenc(g_h[(size_t)n * FEAT + f]);
        if (g != cur) {
            if (cur >= 0) atomicMax(&g_pool[cur * FEAT + f], best);
            cur = g; best = enc;
        } else {
            best = best > enc ? best : enc;
        }
    }
    if (cur >= 0) atomicMax(&g_pool[cur * FEAT + f], best);
}

// ---------------- readout: logits (TF32 dot, matching reference), BCE loss, sigmoid ----------------
__global__ void final_kernel(const float* __restrict__ y, const float* __restrict__ ow,
                             const float* __restrict__ ob, float* __restrict__ out) {
    int g = threadIdx.x;   // 64 threads
    float s = 0.f;
    for (int k = 0; k < FEAT; k++) {
        float v = fdec(g_pool[g * FEAT + k]);
        if (!isfinite(v)) v = 0.f;   // empty-graph guard
        s += tf32r(v) * tf32r(ow[k]);
    }
    float l = s + ob[0];
    out[1 + g] = 1.f / (1.f + expf(-l));
    float bce = fmaxf(l, 0.f) - l * y[g] + log1pf(expf(-fabsf(l)));
    __shared__ float sh[64];
    sh[g] = bce;
    __syncthreads();
    for (int st = 32; st > 0; st >>= 1) {
        if (g < st) sh[g] += sh[g + st];
        __syncthreads();
    }
    if (g == 0) out[0] = sh[0] / (float)N_GRAPHS;
}

// ---------------- launch ----------------
extern "C" void kernel_launch(void* const* d_in, const int* in_sizes, int n_in,
                              void* d_out, int out_size) {
    const int*   word_ids   = (const int*)  d_in[0];
    const int*   edge_src   = (const int*)  d_in[1];
    const int*   edge_dst   = (const int*)  d_in[2];
    const int*   node_gid   = (const int*)  d_in[3];
    const float* y_data     = (const float*)d_in[4];
    const float* word_emb   = (const float*)d_in[5];
    const float* W0         = (const float*)d_in[6];
    const float* al0        = (const float*)d_in[7];
    const float* ar0        = (const float*)d_in[8];
    const float* W1         = (const float*)d_in[9];
    const float* al1        = (const float*)d_in[10];
    const float* ar1        = (const float*)d_in[11];
    const float* out_w      = (const float*)d_in[12];
    const float* out_b      = (const float*)d_in[13];
    float* out = (float*)d_out;

    cudaFuncSetAttribute(gemm_kernel, cudaFuncAttributeMaxDynamicSharedMemorySize, GEMM_SMEM);

    // init + CSR build (deterministic inputs; rebuilt each call)
    init_kernel<<<(N_NODES + 255) / 256, 256>>>();
    deg_kernel<<<(N_EDGES + 255) / 256, 256>>>(edge_dst);
    scan_kernel<<<1, 1024>>>();
    scatter_kernel<<<(N_EDGES + 255) / 256, 256>>>(edge_src, edge_dst);

    int gemm_blocks = (N_NODES + GEMM_ROWS - 1) / GEMM_ROWS;
    int agg_blocks  = (N_NODES * 32 + 255) / 256;

    // layer 0 (gather word embeddings)
    gemm_kernel<<<gemm_blocks, GEMM_THREADS, GEMM_SMEM>>>(word_emb, word_ids, W0, al0, ar0);
    edge_agg_kernel<<<agg_blocks, 256>>>();
    // layer 1 (reads g_h via device symbol; X==null)
    gemm_kernel<<<gemm_blocks, GEMM_THREADS, GEMM_SMEM>>>(nullptr, nullptr, W1, al1, ar1);
    edge_agg_kernel<<<agg_blocks, 256>>>();

    // pooling + readout
    pool_kernel<<<(N_NODES + POOL_CHUNK - 1) / POOL_CHUNK, 128>>>(node_gid);
    final_kernel<<<1, 64>>>(y_data, out_w, out_b, out);
}

// round 5
// speedup vs baseline: 1.3461x; 1.3461x over previous
#include <cuda_runtime.h>
#include <cuda_bf16.h>
#include <math.h>

#define N_NODES 50000
#define N_EDGES 800000
#define VOCAB 15000
#define IN_FEATS 128
#define HIDDEN 32
#define HEADS 4
#define FEAT 128           // HEADS*HIDDEN
#define N_GRAPHS 64
#define NEG_SLOPE 0.2f

// ---------------- scratch (static device globals; no allocation) ----------------
__device__ __align__(16) float g_V[(size_t)VOCAB * FEAT];     // vocab-level layer-0 feat
__device__ __align__(16) float g_elv[VOCAB * HEADS];
__device__ __align__(16) float g_erv[VOCAB * HEADS];
__device__ __align__(16) float g_feat[(size_t)N_NODES * FEAT]; // layer-1 projected feat
__device__ __align__(16) float g_h[(size_t)N_NODES * FEAT];    // layer output / next input
__device__ __align__(16) float g_el[N_NODES * HEADS];
__device__ __align__(16) float g_er[N_NODES * HEADS];
__device__ __align__(16) int   g_deg[N_NODES];
__device__ __align__(16) int   g_cur[N_NODES];
__device__ __align__(16) int   g_off[N_NODES + 4];
__device__ __align__(16) int   g_srcsorted[N_EDGES];
__device__ unsigned g_pool[N_GRAPHS * FEAT];

// TF32 rounding (matches JAX/XLA default f32 matmul precision on GPU)
__device__ __forceinline__ float tf32r(float x) {
    unsigned u;
    asm("cvt.rna.tf32.f32 %0, %1;" : "=r"(u) : "f"(x));
    return __uint_as_float(u);
}
__device__ __forceinline__ float4 tf32r4(float4 v) {
    v.x = tf32r(v.x); v.y = tf32r(v.y); v.z = tf32r(v.z); v.w = tf32r(v.w);
    return v;
}

// order-preserving float <-> uint encode for atomicMax
__device__ __forceinline__ unsigned fenc(float f) {
    unsigned u = __float_as_uint(f);
    return (u & 0x80000000u) ? ~u : (u | 0x80000000u);
}
__device__ __forceinline__ float fdec(unsigned k) {
    return (k & 0x80000000u) ? __uint_as_float(k ^ 0x80000000u) : __uint_as_float(~k);
}
#define ENC_NEG_INF 0x007FFFFFu   // fenc(-inf)

// ---------------- init: zero deg/cur, pool = -inf ----------------
__global__ void init_kernel() {
    int i = blockIdx.x * blockDim.x + threadIdx.x;
    if (i < N_NODES) { g_deg[i] = 0; g_cur[i] = 0; }
    if (i < N_GRAPHS * FEAT) g_pool[i] = ENC_NEG_INF;
}

// ---------------- CSR build ----------------
__global__ void deg_kernel(const int* __restrict__ dst) {
    int i = blockIdx.x * blockDim.x + threadIdx.x;
    if (i < N_EDGES) atomicAdd(&g_deg[dst[i]], 1);
}

// shfl-based two-level scan, int4 I/O, single block of 1024 threads
__global__ void scan_kernel() {
    __shared__ int warp_base[32];
    __shared__ int carry_s;
    int t = threadIdx.x;
    int lane = t & 31, w = t >> 5;
    if (t == 0) carry_s = 0;
    __syncthreads();

    for (int base = 0; base < N_NODES; base += 4096) {
        int idx = base + t * 4;
        int4 v = make_int4(0, 0, 0, 0);
        if (idx + 3 < N_NODES) v = *(const int4*)&g_deg[idx];
        else {
            if (idx     < N_NODES) v.x = g_deg[idx];
            if (idx + 1 < N_NODES) v.y = g_deg[idx + 1];
            if (idx + 2 < N_NODES) v.z = g_deg[idx + 2];
        }
        int tsum = v.x + v.y + v.z + v.w;
        int sc = tsum;                               // inclusive warp scan
#pragma unroll
        for (int d = 1; d < 32; d <<= 1) {
            int o = __shfl_up_sync(0xffffffffu, sc, d);
            if (lane >= d) sc += o;
        }
        if (lane == 31) warp_base[w] = sc;
        __syncthreads();
        if (w == 0) {
            int ws = warp_base[lane];
            int s2 = ws;
#pragma unroll
            for (int d = 1; d < 32; d <<= 1) {
                int o = __shfl_up_sync(0xffffffffu, s2, d);
                if (lane >= d) s2 += o;
            }
            warp_base[lane] = s2 - ws;               // exclusive
        }
        __syncthreads();
        int excl = carry_s + warp_base[w] + (sc - tsum);
        int4 o;
        o.x = excl; o.y = excl + v.x; o.z = o.y + v.y; o.w = o.z + v.z;
        if (idx + 3 < N_NODES) *(int4*)&g_off[idx] = o;
        else {
            if (idx     < N_NODES) g_off[idx]     = o.x;
            if (idx + 1 < N_NODES) g_off[idx + 1] = o.y;
            if (idx + 2 < N_NODES) g_off[idx + 2] = o.z;
        }
        __syncthreads();
        if (t == 1023) carry_s = excl + tsum;        // chunk total
        __syncthreads();
    }
    if (t == 0) g_off[N_NODES] = carry_s;
}

__global__ void scatter_kernel(const int* __restrict__ src, const int* __restrict__ dst) {
    int i = blockIdx.x * blockDim.x + threadIdx.x;
    if (i < N_EDGES) {
        int d = dst[i];
        int pos = g_off[d] + atomicAdd(&g_cur[d], 1);
        g_srcsorted[pos] = src[i];
    }
}

// ---------------- fused GEMM + el/er, register-blocked 4x4 ----------------
// Fout = round(X) @ round(W); el/er via in-register head reduction.
// X==null -> read g_h. Operands TF32-rounded (reference matmul precision).
#define GR 32
#define GEMM_THREADS 256
#define GEMM_SMEM ((128*128 + GR*128 + 256) * 4)

__global__ void gemm_kernel(const float* __restrict__ X, int nrows,
                            const float* __restrict__ W,
                            const float* __restrict__ al, const float* __restrict__ ar,
                            float* __restrict__ Fout,
                            float* __restrict__ elOut, float* __restrict__ erOut) {
    extern __shared__ float sh[];
    float* Ws  = sh;                 // [128][128] k-major rows
    float* Hs  = Ws + 128 * 128;     // [32][128]
    float* als = Hs + GR * 128;      // 128
    float* ars = als + 128;          // 128

    int t = threadIdx.x;
    for (int i = t; i < 128 * 128 / 4; i += GEMM_THREADS)
        ((float4*)Ws)[i] = tf32r4(((const float4*)W)[i]);
    if (t < 128) { als[t] = al[t]; ars[t] = ar[t]; }

    int row0 = blockIdx.x * GR;
    for (int i = t; i < GR * 32; i += GEMM_THREADS) {
        int r = i >> 5, c4 = i & 31;
        int node = row0 + r;
        float4 h4 = make_float4(0.f, 0.f, 0.f, 0.f);
        if (node < nrows) {
            h4 = X ? ((const float4*)(X + (size_t)node * 128))[c4]
                   : ((const float4*)(g_h + (size_t)node * 128))[c4];
            h4 = tf32r4(h4);
        }
        ((float4*)Hs)[i] = h4;
    }
    __syncthreads();

    int tx = t & 31;          // col group: cols tx*4 .. tx*4+3 (all in head tx/8)
    int ty = t >> 5;          // row group: rows ty*4 .. ty*4+3 (uniform per warp)
    float acc[4][4];
#pragma unroll
    for (int r = 0; r < 4; r++)
#pragma unroll
        for (int c = 0; c < 4; c++) acc[r][c] = 0.f;

#pragma unroll 4
    for (int kk = 0; kk < 128; kk += 4) {
        float4 wv[4], hv[4];
#pragma unroll
        for (int q = 0; q < 4; q++)
            wv[q] = *(const float4*)&Ws[(kk + q) * 128 + tx * 4];   // conflict-free
#pragma unroll
        for (int r = 0; r < 4; r++)
            hv[r] = *(const float4*)&Hs[(ty * 4 + r) * 128 + kk];   // warp broadcast
#pragma unroll
        for (int r = 0; r < 4; r++) {
            const float* h = (const float*)&hv[r];
#pragma unroll
            for (int c = 0; c < 4; c++) {
                const float* w0 = (const float*)&wv[0];
                const float* w1 = (const float*)&wv[1];
                const float* w2 = (const float*)&wv[2];
                const float* w3 = (const float*)&wv[3];
                acc[r][c] += h[0] * w0[c] + h[1] * w1[c] + h[2] * w2[c] + h[3] * w3[c];
            }
        }
    }

    int j0 = tx * 4;
    int head = tx >> 3;
    float a0 = als[j0], a1 = als[j0 + 1], a2 = als[j0 + 2], a3 = als[j0 + 3];
    float b0 = ars[j0], b1 = ars[j0 + 1], b2 = ars[j0 + 2], b3 = ars[j0 + 3];
#pragma unroll
    for (int r = 0; r < 4; r++) {
        int node = row0 + ty * 4 + r;
        float pa = acc[r][0] * a0 + acc[r][1] * a1 + acc[r][2] * a2 + acc[r][3] * a3;
        float pb = acc[r][0] * b0 + acc[r][1] * b1 + acc[r][2] * b2 + acc[r][3] * b3;
#pragma unroll
        for (int s = 4; s > 0; s >>= 1) {       // reduce over 8-lane head group
            pa += __shfl_xor_sync(0xffffffffu, pa, s);
            pb += __shfl_xor_sync(0xffffffffu, pb, s);
        }
        if (node < nrows) {
            float4 o = make_float4(acc[r][0], acc[r][1], acc[r][2], acc[r][3]);
            *(float4*)&Fout[(size_t)node * 128 + j0] = o;
            if ((tx & 7) == 0) {
                elOut[node * HEADS + head] = pa;
                erOut[node * HEADS + head] = pb;
            }
        }
    }
}

// ---------------- edge aggregation: one warp per dst node, online softmax ----------------
// wid != null -> layer 0: feature/attention rows gathered through word_ids.
__global__ void edge_agg_kernel(const int* __restrict__ wid) {
    int gw = (blockIdx.x * blockDim.x + threadIdx.x) >> 5;
    int lane = threadIdx.x & 31;
    if (gw >= N_NODES) return;
    int n = gw;

    const float* F   = wid ? g_V   : g_feat;
    const float* ELV = wid ? g_elv : g_el;
    const float* ERV = wid ? g_erv : g_er;

    int nr = wid ? wid[n] : n;
    float4 er4 = *(const float4*)&ERV[nr * HEADS];
    float er[4] = {er4.x, er4.y, er4.z, er4.w};
    float m[4], den[4], acc[4];
#pragma unroll
    for (int h = 0; h < 4; h++) { m[h] = -INFINITY; den[h] = 0.f; acc[h] = 0.f; }

    int s = g_off[n], e = g_off[n + 1];

    // software-pipelined: index/attn loads for edge i+1 issued during edge i
    int r_cur = 0;
    float4 el4_cur = make_float4(0.f, 0.f, 0.f, 0.f);
    if (s < e) {
        int src = g_srcsorted[s];
        r_cur = wid ? __ldg(&wid[src]) : src;
        el4_cur = *(const float4*)&ELV[r_cur * HEADS];
    }
    for (int i = s; i < e; i++) {
        int r = r_cur;
        float4 el4 = el4_cur;
        if (i + 1 < e) {
            int src = g_srcsorted[i + 1];
            r_cur = wid ? __ldg(&wid[src]) : src;
            el4_cur = *(const float4*)&ELV[r_cur * HEADS];
        }
        const float* f = F + (size_t)r * FEAT;
        float f0 = __ldg(&f[lane]);
        float f1 = __ldg(&f[32 + lane]);
        float f2 = __ldg(&f[64 + lane]);
        float f3 = __ldg(&f[96 + lane]);
        float fv[4] = {f0, f1, f2, f3};
        float el[4] = {el4.x, el4.y, el4.z, el4.w};
#pragma unroll
        for (int h = 0; h < 4; h++) {
            float x = el[h] + er[h];
            x = (x > 0.f) ? x : NEG_SLOPE * x;
            if (x <= m[h]) {
                float p = __expf(x - m[h]);
                den[h] += p;
                acc[h] += p * fv[h];
            } else {
                float sc = __expf(m[h] - x);     // = 0 when m = -inf
                den[h] = den[h] * sc + 1.f;
                acc[h] = acc[h] * sc + fv[h];
                m[h] = x;
            }
        }
    }
#pragma unroll
    for (int h = 0; h < 4; h++) {
        float o = acc[h] / (den[h] + 1e-10f);
        o = (o > 0.f) ? o : expm1f(o);           // elu
        g_h[(size_t)n * FEAT + h * 32 + lane] = o;
    }
}

// ---------------- per-graph max pool (node_graph_id sorted -> run-length local max) ----------------
#define POOL_CHUNK 128
__global__ void pool_kernel(const int* __restrict__ gid) {
    int f = threadIdx.x;   // 128 threads = feature dims
    int n0 = blockIdx.x * POOL_CHUNK;
    int n1 = n0 + POOL_CHUNK; if (n1 > N_NODES) n1 = N_NODES;
    int cur = -1;
    unsigned best = 0;
    for (int n = n0; n < n1; n++) {
        int g = gid[n];                               // broadcast load
        unsigned enc = fenc(g_h[(size_t)n * FEAT + f]);
        if (g != cur) {
            if (cur >= 0) atomicMax(&g_pool[cur * FEAT + f], best);
            cur = g; best = enc;
        } else {
            best = best > enc ? best : enc;
        }
    }
    if (cur >= 0) atomicMax(&g_pool[cur * FEAT + f], best);
}

// ---------------- readout: logits (TF32 dot, matching reference), BCE loss, sigmoid ----------------
__global__ void final_kernel(const float* __restrict__ y, const float* __restrict__ ow,
                             const float* __restrict__ ob, float* __restrict__ out) {
    int g = threadIdx.x;   // 64 threads
    float s = 0.f;
    for (int k = 0; k < FEAT; k++) {
        float v = fdec(g_pool[g * FEAT + k]);
        if (!isfinite(v)) v = 0.f;   // empty-graph guard
        s += tf32r(v) * tf32r(ow[k]);
    }
    float l = s + ob[0];
    out[1 + g] = 1.f / (1.f + expf(-l));
    float bce = fmaxf(l, 0.f) - l * y[g] + log1pf(expf(-fabsf(l)));
    __shared__ float sh[64];
    sh[g] = bce;
    __syncthreads();
    for (int st = 32; st > 0; st >>= 1) {
        if (g < st) sh[g] += sh[g + st];
        __syncthreads();
    }
    if (g == 0) out[0] = sh[0] / (float)N_GRAPHS;
}

// device-symbol output pointers for the gemm kernel are selected host-side via
// separate launches reading/writing the symbols directly is not possible, so we
// fetch symbol addresses once per launch call (host API, no allocation, capture-safe:
// it enqueues no work).
extern "C" void kernel_launch(void* const* d_in, const int* in_sizes, int n_in,
                              void* d_out, int out_size) {
    const int*   word_ids   = (const int*)  d_in[0];
    const int*   edge_src   = (const int*)  d_in[1];
    const int*   edge_dst   = (const int*)  d_in[2];
    const int*   node_gid   = (const int*)  d_in[3];
    const float* y_data     = (const float*)d_in[4];
    const float* word_emb   = (const float*)d_in[5];
    const float* W0         = (const float*)d_in[6];
    const float* al0        = (const float*)d_in[7];
    const float* ar0        = (const float*)d_in[8];
    const float* W1         = (const float*)d_in[9];
    const float* al1        = (const float*)d_in[10];
    const float* ar1        = (const float*)d_in[11];
    const float* out_w      = (const float*)d_in[12];
    const float* out_b      = (const float*)d_in[13];
    float* out = (float*)d_out;

    static float *pV = nullptr, *pElv, *pErv, *pFeat, *pEl, *pEr;
    if (!pV) {   // resolved once; pure address lookup, deterministic
        cudaGetSymbolAddress((void**)&pV,    g_V);
        cudaGetSymbolAddress((void**)&pElv,  g_elv);
        cudaGetSymbolAddress((void**)&pErv,  g_erv);
        cudaGetSymbolAddress((void**)&pFeat, g_feat);
        cudaGetSymbolAddress((void**)&pEl,   g_el);
        cudaGetSymbolAddress((void**)&pEr,   g_er);
        cudaFuncSetAttribute(gemm_kernel, cudaFuncAttributeMaxDynamicSharedMemorySize, GEMM_SMEM);
    }

    // CSR build (rebuilt each call; deterministic inputs)
    init_kernel<<<(N_NODES + 255) / 256, 256>>>();
    deg_kernel<<<(N_EDGES + 255) / 256, 256>>>(edge_dst);
    scan_kernel<<<1, 1024>>>();
    scatter_kernel<<<(N_EDGES + 255) / 256, 256>>>(edge_src, edge_dst);

    int agg_blocks = (N_NODES * 32 + 255) / 256;

    // layer 0: GEMM over distinct vocab rows only (15000 instead of 50000)
    gemm_kernel<<<(VOCAB + GR - 1) / GR, GEMM_THREADS, GEMM_SMEM>>>(
        word_emb, VOCAB, W0, al0, ar0, pV, pElv, pErv);
    edge_agg_kernel<<<agg_blocks, 256>>>(word_ids);

    // layer 1: full node GEMM reading g_h (X==null)
    gemm_kernel<<<(N_NODES + GR - 1) / GR, GEMM_THREADS, GEMM_SMEM>>>(
        nullptr, N_NODES, W1, al1, ar1, pFeat, pEl, pEr);
    edge_agg_kernel<<<agg_blocks, 256>>>(nullptr);

    // pooling + readout
    pool_kernel<<<(N_NODES + POOL_CHUNK - 1) / POOL_CHUNK, 128>>>(node_gid);
    final_kernel<<<1, 64>>>(y_data, out_w, out_b, out);
}

// round 6
// speedup vs baseline: 1.3493x; 1.0024x over previous
#include <cuda_runtime.h>
#include <cuda_bf16.h>
#include <math.h>

#define N_NODES 50000
#define N_EDGES 800000
#define VOCAB 15000
#define IN_FEATS 128
#define HIDDEN 32
#define HEADS 4
#define FEAT 128           // HEADS*HIDDEN
#define N_GRAPHS 64
#define NEG_SLOPE 0.2f

// ---------------- scratch (static device globals; no allocation) ----------------
// feat tables stored HEAD-INTERLEAVED: row[d*4 + h] = feat[h*32 + d]
__device__ __align__(16) float g_V[(size_t)VOCAB * FEAT];      // vocab-level layer-0 feat (interleaved)
__device__ __align__(16) float g_elv[VOCAB * HEADS];
__device__ __align__(16) float g_erv[VOCAB * HEADS];
__device__ __align__(16) float g_feat[(size_t)N_NODES * FEAT]; // layer-1 feat (interleaved)
__device__ __align__(16) float g_h[(size_t)N_NODES * FEAT];    // layer output (standard layout)
__device__ __align__(16) float g_el[N_NODES * HEADS];
__device__ __align__(16) float g_er[N_NODES * HEADS];
__device__ __align__(16) int   g_deg[N_NODES];
__device__ __align__(16) int   g_cur[N_NODES];
__device__ __align__(16) int   g_off[N_NODES + 4];
__device__ __align__(16) int   g_srcsorted[N_EDGES];
__device__ unsigned g_pool[N_GRAPHS * FEAT];

// TF32 rounding (matches JAX/XLA default f32 matmul precision on GPU)
__device__ __forceinline__ float tf32r(float x) {
    unsigned u;
    asm("cvt.rna.tf32.f32 %0, %1;" : "=r"(u) : "f"(x));
    return __uint_as_float(u);
}
__device__ __forceinline__ float4 tf32r4(float4 v) {
    v.x = tf32r(v.x); v.y = tf32r(v.y); v.z = tf32r(v.z); v.w = tf32r(v.w);
    return v;
}

// order-preserving float <-> uint encode for atomicMax
__device__ __forceinline__ unsigned fenc(float f) {
    unsigned u = __float_as_uint(f);
    return (u & 0x80000000u) ? ~u : (u | 0x80000000u);
}
__device__ __forceinline__ float fdec(unsigned k) {
    return (k & 0x80000000u) ? __uint_as_float(k ^ 0x80000000u) : __uint_as_float(~k);
}
#define ENC_NEG_INF 0x007FFFFFu   // fenc(-inf)

// ---------------- init: zero deg/cur, pool = -inf ----------------
__global__ void init_kernel() {
    int i = blockIdx.x * blockDim.x + threadIdx.x;
    if (i < N_NODES) { g_deg[i] = 0; g_cur[i] = 0; }
    if (i < N_GRAPHS * FEAT) g_pool[i] = ENC_NEG_INF;
}

// ---------------- CSR build ----------------
__global__ void deg_kernel(const int4* __restrict__ dst4) {
    int i = blockIdx.x * blockDim.x + threadIdx.x;   // i indexes groups of 4 edges
    if (i < N_EDGES / 4) {
        int4 d = dst4[i];
        atomicAdd(&g_deg[d.x], 1);
        atomicAdd(&g_deg[d.y], 1);
        atomicAdd(&g_deg[d.z], 1);
        atomicAdd(&g_deg[d.w], 1);
    }
}

// shfl-based two-level scan, int4 I/O, single block of 1024 threads
__global__ void scan_kernel() {
    __shared__ int warp_base[32];
    __shared__ int carry_s;
    int t = threadIdx.x;
    int lane = t & 31, w = t >> 5;
    if (t == 0) carry_s = 0;
    __syncthreads();

    for (int base = 0; base < N_NODES; base += 4096) {
        int idx = base + t * 4;
        int4 v = make_int4(0, 0, 0, 0);
        if (idx + 3 < N_NODES) v = *(const int4*)&g_deg[idx];
        else {
            if (idx     < N_NODES) v.x = g_deg[idx];
            if (idx + 1 < N_NODES) v.y = g_deg[idx + 1];
            if (idx + 2 < N_NODES) v.z = g_deg[idx + 2];
        }
        int tsum = v.x + v.y + v.z + v.w;
        int sc = tsum;                               // inclusive warp scan
#pragma unroll
        for (int d = 1; d < 32; d <<= 1) {
            int o = __shfl_up_sync(0xffffffffu, sc, d);
            if (lane >= d) sc += o;
        }
        if (lane == 31) warp_base[w] = sc;
        __syncthreads();
        if (w == 0) {
            int ws = warp_base[lane];
            int s2 = ws;
#pragma unroll
            for (int d = 1; d < 32; d <<= 1) {
                int o = __shfl_up_sync(0xffffffffu, s2, d);
                if (lane >= d) s2 += o;
            }
            warp_base[lane] = s2 - ws;               // exclusive
        }
        __syncthreads();
        int excl = carry_s + warp_base[w] + (sc - tsum);
        int4 o;
        o.x = excl; o.y = excl + v.x; o.z = o.y + v.y; o.w = o.z + v.z;
        if (idx + 3 < N_NODES) *(int4*)&g_off[idx] = o;
        else {
            if (idx     < N_NODES) g_off[idx]     = o.x;
            if (idx + 1 < N_NODES) g_off[idx + 1] = o.y;
            if (idx + 2 < N_NODES) g_off[idx + 2] = o.z;
        }
        __syncthreads();
        if (t == 1023) carry_s = excl + tsum;        // chunk total
        __syncthreads();
    }
    if (t == 0) g_off[N_NODES] = carry_s;
}

__global__ void scatter_kernel(const int4* __restrict__ src4, const int4* __restrict__ dst4) {
    int i = blockIdx.x * blockDim.x + threadIdx.x;
    if (i < N_EDGES / 4) {
        int4 s = src4[i];
        int4 d = dst4[i];
        g_srcsorted[g_off[d.x] + atomicAdd(&g_cur[d.x], 1)] = s.x;
        g_srcsorted[g_off[d.y] + atomicAdd(&g_cur[d.y], 1)] = s.y;
        g_srcsorted[g_off[d.z] + atomicAdd(&g_cur[d.z], 1)] = s.z;
        g_srcsorted[g_off[d.w] + atomicAdd(&g_cur[d.w], 1)] = s.w;
    }
}

// ---------------- fused GEMM + el/er, register-blocked 4x4 ----------------
// Fout (HEAD-INTERLEAVED) = round(X) @ round(W); el/er via in-register reduce.
// X==null -> read g_h. Operands TF32-rounded (reference matmul precision).
#define GR 32
#define GEMM_THREADS 256
#define GEMM_SMEM ((128*128 + GR*128 + 256) * 4)

__global__ void gemm_kernel(const float* __restrict__ X, int nrows,
                            const float* __restrict__ W,
                            const float* __restrict__ al, const float* __restrict__ ar,
                            float* __restrict__ Fout,
                            float* __restrict__ elOut, float* __restrict__ erOut) {
    extern __shared__ float sh[];
    float* Ws  = sh;                 // [128][128] k-major rows
    float* Hs  = Ws + 128 * 128;     // [32][128]
    float* als = Hs + GR * 128;      // 128
    float* ars = als + 128;          // 128

    int t = threadIdx.x;
    for (int i = t; i < 128 * 128 / 4; i += GEMM_THREADS)
        ((float4*)Ws)[i] = tf32r4(((const float4*)W)[i]);
    if (t < 128) { als[t] = al[t]; ars[t] = ar[t]; }

    int row0 = blockIdx.x * GR;
    for (int i = t; i < GR * 32; i += GEMM_THREADS) {
        int r = i >> 5, c4 = i & 31;
        int node = row0 + r;
        float4 h4 = make_float4(0.f, 0.f, 0.f, 0.f);
        if (node < nrows) {
            h4 = X ? ((const float4*)(X + (size_t)node * 128))[c4]
                   : ((const float4*)(g_h + (size_t)node * 128))[c4];
            h4 = tf32r4(h4);
        }
        ((float4*)Hs)[i] = h4;
    }
    __syncthreads();

    int tx = t & 31;          // col group: cols tx*4 .. tx*4+3 (all in head tx>>3)
    int ty = t >> 5;          // row group: rows ty*4 .. ty*4+3 (uniform per warp)
    float acc[4][4];
#pragma unroll
    for (int r = 0; r < 4; r++)
#pragma unroll
        for (int c = 0; c < 4; c++) acc[r][c] = 0.f;

#pragma unroll 4
    for (int kk = 0; kk < 128; kk += 4) {
        float4 wv[4], hv[4];
#pragma unroll
        for (int q = 0; q < 4; q++)
            wv[q] = *(const float4*)&Ws[(kk + q) * 128 + tx * 4];   // conflict-free
#pragma unroll
        for (int r = 0; r < 4; r++)
            hv[r] = *(const float4*)&Hs[(ty * 4 + r) * 128 + kk];   // warp broadcast
#pragma unroll
        for (int r = 0; r < 4; r++) {
            const float* h = (const float*)&hv[r];
#pragma unroll
            for (int c = 0; c < 4; c++) {
                const float* w0 = (const float*)&wv[0];
                const float* w1 = (const float*)&wv[1];
                const float* w2 = (const float*)&wv[2];
                const float* w3 = (const float*)&wv[3];
                acc[r][c] += h[0] * w0[c] + h[1] * w1[c] + h[2] * w2[c] + h[3] * w3[c];
            }
        }
    }

    int j0 = tx * 4;
    int head = tx >> 3;             // j0/32
    int d0 = (tx & 7) * 4;          // j0%32
    float a0 = als[j0], a1 = als[j0 + 1], a2 = als[j0 + 2], a3 = als[j0 + 3];
    float b0 = ars[j0], b1 = ars[j0 + 1], b2 = ars[j0 + 2], b3 = ars[j0 + 3];
#pragma unroll
    for (int r = 0; r < 4; r++) {
        int node = row0 + ty * 4 + r;
        float pa = acc[r][0] * a0 + acc[r][1] * a1 + acc[r][2] * a2 + acc[r][3] * a3;
        float pb = acc[r][0] * b0 + acc[r][1] * b1 + acc[r][2] * b2 + acc[r][3] * b3;
#pragma unroll
        for (int s = 4; s > 0; s >>= 1) {       // reduce over 8-lane head group
            pa += __shfl_xor_sync(0xffffffffu, pa, s);
            pb += __shfl_xor_sync(0xffffffffu, pb, s);
        }
        if (node < nrows) {
            float* frow = Fout + (size_t)node * 128;
            // head-interleaved store: col j -> offset (j%32)*4 + head
            frow[(d0 + 0) * 4 + head] = acc[r][0];
            frow[(d0 + 1) * 4 + head] = acc[r][1];
            frow[(d0 + 2) * 4 + head] = acc[r][2];
            frow[(d0 + 3) * 4 + head] = acc[r][3];
            if ((tx & 7) == 0) {
                elOut[node * HEADS + head] = pa;
                erOut[node * HEADS + head] = pb;
            }
        }
    }
}

// ---------------- edge aggregation: one warp per dst node, online softmax ----------------
// wid != null -> layer 0 (vocab tables gathered through word_ids).
// Fully software-pipelined: idx, el and feat(float4) of edge i+1 in flight during edge i.
__global__ void edge_agg_kernel(const int* __restrict__ wid) {
    int gw = (blockIdx.x * blockDim.x + threadIdx.x) >> 5;
    int lane = threadIdx.x & 31;
    if (gw >= N_NODES) return;
    int n = gw;

    const float* F   = wid ? g_V   : g_feat;
    const float* ELV = wid ? g_elv : g_el;
    const float* ERV = wid ? g_erv : g_er;

    int nr = wid ? __ldg(&wid[n]) : n;
    float4 er4 = *(const float4*)&ERV[nr * HEADS];
    float er[4] = {er4.x, er4.y, er4.z, er4.w};
    float m[4], den[4], acc[4];
#pragma unroll
    for (int h = 0; h < 4; h++) { m[h] = -INFINITY; den[h] = 0.f; acc[h] = 0.f; }

    int s = g_off[n], e = g_off[n + 1];

    float4 el_p = make_float4(0.f, 0.f, 0.f, 0.f);
    float4 fv_p = make_float4(0.f, 0.f, 0.f, 0.f);
    if (s < e) {
        int src = __ldg(&g_srcsorted[s]);
        int r = wid ? __ldg(&wid[src]) : src;
        el_p = *(const float4*)&ELV[r * HEADS];
        fv_p = __ldg((const float4*)(F + (size_t)r * FEAT) + lane);  // [h0,h1,h2,h3] for dim=lane
    }
    for (int i = s; i < e; i++) {
        float4 el4 = el_p;
        float4 fv4 = fv_p;
        if (i + 1 < e) {
            int src = __ldg(&g_srcsorted[i + 1]);
            int r = wid ? __ldg(&wid[src]) : src;
            el_p = *(const float4*)&ELV[r * HEADS];
            fv_p = __ldg((const float4*)(F + (size_t)r * FEAT) + lane);
        }
        float el[4] = {el4.x, el4.y, el4.z, el4.w};
        float fv[4] = {fv4.x, fv4.y, fv4.z, fv4.w};
#pragma unroll
        for (int h = 0; h < 4; h++) {
            float x = el[h] + er[h];
            x = (x > 0.f) ? x : NEG_SLOPE * x;
            if (x <= m[h]) {
                float p = __expf(x - m[h]);
                den[h] += p;
                acc[h] += p * fv[h];
            } else {
                float sc = __expf(m[h] - x);     // = 0 when m = -inf
                den[h] = den[h] * sc + 1.f;
                acc[h] = acc[h] * sc + fv[h];
                m[h] = x;
            }
        }
    }
#pragma unroll
    for (int h = 0; h < 4; h++) {
        float o = acc[h] / (den[h] + 1e-10f);
        o = (o > 0.f) ? o : expm1f(o);           // elu
        g_h[(size_t)n * FEAT + h * 32 + lane] = o;   // standard layout for next gemm/pool
    }
}

// ---------------- per-graph max pool (node_graph_id sorted -> run-length local max) ----------------
#define POOL_CHUNK 128
__global__ void pool_kernel(const int* __restrict__ gid) {
    int f = threadIdx.x;   // 128 threads = feature dims
    int n0 = blockIdx.x * POOL_CHUNK;
    int n1 = n0 + POOL_CHUNK; if (n1 > N_NODES) n1 = N_NODES;
    int cur = -1;
    unsigned best = 0;
    for (int n = n0; n < n1; n++) {
        int g = gid[n];                               // broadcast load
        unsigned enc = fenc(g_h[(size_t)n * FEAT + f]);
        if (g != cur) {
            if (cur >= 0) atomicMax(&g_pool[cur * FEAT + f], best);
            cur = g; best = enc;
        } else {
            best = best > enc ? best : enc;
        }
    }
    if (cur >= 0) atomicMax(&g_pool[cur * FEAT + f], best);
}

// ---------------- readout: logits (TF32 dot, matching reference), BCE loss, sigmoid ----------------
__global__ void final_kernel(const float* __restrict__ y, const float* __restrict__ ow,
                             const float* __restrict__ ob, float* __restrict__ out) {
    int g = threadIdx.x;   // 64 threads
    float s = 0.f;
    for (int k = 0; k < FEAT; k++) {
        float v = fdec(g_pool[g * FEAT + k]);
        if (!isfinite(v)) v = 0.f;   // empty-graph guard
        s += tf32r(v) * tf32r(ow[k]);
    }
    float l = s + ob[0];
    out[1 + g] = 1.f / (1.f + expf(-l));
    float bce = fmaxf(l, 0.f) - l * y[g] + log1pf(expf(-fabsf(l)));
    __shared__ float sh[64];
    sh[g] = bce;
    __syncthreads();
    for (int st = 32; st > 0; st >>= 1) {
        if (g < st) sh[g] += sh[g + st];
        __syncthreads();
    }
    if (g == 0) out[0] = sh[0] / (float)N_GRAPHS;
}

extern "C" void kernel_launch(void* const* d_in, const int* in_sizes, int n_in,
                              void* d_out, int out_size) {
    const int*   word_ids   = (const int*)  d_in[0];
    const int*   edge_src   = (const int*)  d_in[1];
    const int*   edge_dst   = (const int*)  d_in[2];
    const int*   node_gid   = (const int*)  d_in[3];
    const float* y_data     = (const float*)d_in[4];
    const float* word_emb   = (const float*)d_in[5];
    const float* W0         = (const float*)d_in[6];
    const float* al0        = (const float*)d_in[7];
    const float* ar0        = (const float*)d_in[8];
    const float* W1         = (const float*)d_in[9];
    const float* al1        = (const float*)d_in[10];
    const float* ar1        = (const float*)d_in[11];
    const float* out_w      = (const float*)d_in[12];
    const float* out_b      = (const float*)d_in[13];
    float* out = (float*)d_out;

    static float *pV = nullptr, *pElv, *pErv, *pFeat, *pEl, *pEr;
    if (!pV) {   // resolved once; pure address lookup, deterministic, enqueues no work
        cudaGetSymbolAddress((void**)&pV,    g_V);
        cudaGetSymbolAddress((void**)&pElv,  g_elv);
        cudaGetSymbolAddress((void**)&pErv,  g_erv);
        cudaGetSymbolAddress((void**)&pFeat, g_feat);
        cudaGetSymbolAddress((void**)&pEl,   g_el);
        cudaGetSymbolAddress((void**)&pEr,   g_er);
        cudaFuncSetAttribute(gemm_kernel, cudaFuncAttributeMaxDynamicSharedMemorySize, GEMM_SMEM);
    }

    // CSR build (rebuilt each call; deterministic inputs). N_EDGES % 4 == 0.
    init_kernel<<<(N_NODES + 255) / 256, 256>>>();
    deg_kernel<<<(N_EDGES / 4 + 255) / 256, 256>>>((const int4*)edge_dst);
    scan_kernel<<<1, 1024>>>();
    scatter_kernel<<<(N_EDGES / 4 + 255) / 256, 256>>>((const int4*)edge_src, (const int4*)edge_dst);

    int agg_blocks = (N_NODES * 32 + 255) / 256;

    // layer 0: GEMM over distinct vocab rows only (15000 instead of 50000)
    gemm_kernel<<<(VOCAB + GR - 1) / GR, GEMM_THREADS, GEMM_SMEM>>>(
        word_emb, VOCAB, W0, al0, ar0, pV, pElv, pErv);
    edge_agg_kernel<<<agg_blocks, 256>>>(word_ids);

    // layer 1: full node GEMM reading g_h (X==null)
    gemm_kernel<<<(N_NODES + GR - 1) / GR, GEMM_THREADS, GEMM_SMEM>>>(
        nullptr, N_NODES, W1, al1, ar1, pFeat, pEl, pEr);
    edge_agg_kernel<<<agg_blocks, 256>>>(nullptr);

    // pooling + readout
    pool_kernel<<<(N_NODES + POOL_CHUNK - 1) / POOL_CHUNK, 128>>>(node_gid);
    final_kernel<<<1, 64>>>(y_data, out_w, out_b, out);
}

// round 7
// speedup vs baseline: 1.5797x; 1.1707x over previous
#include <cuda_runtime.h>
#include <cuda_bf16.h>
#include <math.h>

#define N_NODES 50000
#define N_EDGES 800000
#define VOCAB 15000
#define IN_FEATS 128
#define HIDDEN 32
#define HEADS 4
#define FEAT 128           // HEADS*HIDDEN
#define N_GRAPHS 64
#define NEG_SLOPE 0.2f

// ---------------- scratch (static device globals; no allocation) ----------------
// feat tables stored HEAD-INTERLEAVED: row[d*4 + h] = feat[h*32 + d]
__device__ __align__(16) float g_V[(size_t)VOCAB * FEAT];      // vocab-level layer-0 feat (interleaved)
__device__ __align__(16) float g_elv[VOCAB * HEADS];
__device__ __align__(16) float g_erv[VOCAB * HEADS];
__device__ __align__(16) float g_feat[(size_t)N_NODES * FEAT]; // layer-1 feat (interleaved)
__device__ __align__(16) float g_h[(size_t)N_NODES * FEAT];    // layer output (standard layout)
__device__ __align__(16) float g_el[N_NODES * HEADS];
__device__ __align__(16) float g_er[N_NODES * HEADS];
__device__ __align__(16) int   g_deg[N_NODES];                 // zeroed by cleanup (and static-init)
__device__ __align__(16) int   g_cur[N_NODES];                 // zeroed by cleanup (and static-init)
__device__ __align__(16) int   g_off[N_NODES + 4];
__device__ __align__(16) int   g_srcsorted[N_EDGES];
__device__ unsigned g_pool[N_GRAPHS * FEAT];                   // re-armed by cleanup; 0 is also a valid identity

// TF32 rounding (matches JAX/XLA default f32 matmul precision on GPU)
__device__ __forceinline__ float tf32r(float x) {
    unsigned u;
    asm("cvt.rna.tf32.f32 %0, %1;" : "=r"(u) : "f"(x));
    return __uint_as_float(u);
}
__device__ __forceinline__ float4 tf32r4(float4 v) {
    v.x = tf32r(v.x); v.y = tf32r(v.y); v.z = tf32r(v.z); v.w = tf32r(v.w);
    return v;
}

// order-preserving float <-> uint encode for atomicMax
__device__ __forceinline__ unsigned fenc(float f) {
    unsigned u = __float_as_uint(f);
    return (u & 0x80000000u) ? ~u : (u | 0x80000000u);
}
__device__ __forceinline__ float fdec(unsigned k) {
    return (k & 0x80000000u) ? __uint_as_float(k ^ 0x80000000u) : __uint_as_float(~k);
}
#define ENC_NEG_INF 0x007FFFFFu   // fenc(-inf)

// ---------------- CSR build ----------------
__global__ void deg_kernel(const int* __restrict__ dst) {
    int i = blockIdx.x * blockDim.x + threadIdx.x;
    if (i < N_EDGES) atomicAdd(&g_deg[dst[i]], 1);
}

// shfl-based two-level scan, int4 I/O, single block of 1024 threads
__global__ void scan_kernel() {
    __shared__ int warp_base[32];
    __shared__ int carry_s;
    int t = threadIdx.x;
    int lane = t & 31, w = t >> 5;
    if (t == 0) carry_s = 0;
    __syncthreads();

    for (int base = 0; base < N_NODES; base += 4096) {
        int idx = base + t * 4;
        int4 v = make_int4(0, 0, 0, 0);
        if (idx + 3 < N_NODES) v = *(const int4*)&g_deg[idx];
        else {
            if (idx     < N_NODES) v.x = g_deg[idx];
            if (idx + 1 < N_NODES) v.y = g_deg[idx + 1];
            if (idx + 2 < N_NODES) v.z = g_deg[idx + 2];
        }
        int tsum = v.x + v.y + v.z + v.w;
        int sc = tsum;                               // inclusive warp scan
#pragma unroll
        for (int d = 1; d < 32; d <<= 1) {
            int o = __shfl_up_sync(0xffffffffu, sc, d);
            if (lane >= d) sc += o;
        }
        if (lane == 31) warp_base[w] = sc;
        __syncthreads();
        if (w == 0) {
            int ws = warp_base[lane];
            int s2 = ws;
#pragma unroll
            for (int d = 1; d < 32; d <<= 1) {
                int o = __shfl_up_sync(0xffffffffu, s2, d);
                if (lane >= d) s2 += o;
            }
            warp_base[lane] = s2 - ws;               // exclusive
        }
        __syncthreads();
        int excl = carry_s + warp_base[w] + (sc - tsum);
        int4 o;
        o.x = excl; o.y = excl + v.x; o.z = o.y + v.y; o.w = o.z + v.z;
        if (idx + 3 < N_NODES) *(int4*)&g_off[idx] = o;
        else {
            if (idx     < N_NODES) g_off[idx]     = o.x;
            if (idx + 1 < N_NODES) g_off[idx + 1] = o.y;
            if (idx + 2 < N_NODES) g_off[idx + 2] = o.z;
        }
        __syncthreads();
        if (t == 1023) carry_s = excl + tsum;        // chunk total
        __syncthreads();
    }
    if (t == 0) g_off[N_NODES] = carry_s;
}

__global__ void scatter_kernel(const int* __restrict__ src, const int* __restrict__ dst) {
    int i = blockIdx.x * blockDim.x + threadIdx.x;
    if (i < N_EDGES) {
        int d = dst[i];
        int pos = g_off[d] + atomicAdd(&g_cur[d], 1);
        g_srcsorted[pos] = src[i];
    }
}

// ---------------- fused GEMM + el/er, register-blocked 4x4 ----------------
// Fout (HEAD-INTERLEAVED) = round(X) @ round(W); el/er via in-register reduce.
// X==null -> read g_h. Operands TF32-rounded (reference matmul precision).
#define GR 32
#define GEMM_THREADS 256
#define GEMM_SMEM ((128*128 + GR*128 + 256) * 4)

__global__ void gemm_kernel(const float* __restrict__ X, int nrows,
                            const float* __restrict__ W,
                            const float* __restrict__ al, const float* __restrict__ ar,
                            float* __restrict__ Fout,
                            float* __restrict__ elOut, float* __restrict__ erOut) {
    extern __shared__ float sh[];
    float* Ws  = sh;                 // [128][128] k-major rows
    float* Hs  = Ws + 128 * 128;     // [32][128]
    float* als = Hs + GR * 128;      // 128
    float* ars = als + 128;          // 128

    int t = threadIdx.x;
    for (int i = t; i < 128 * 128 / 4; i += GEMM_THREADS)
        ((float4*)Ws)[i] = tf32r4(((const float4*)W)[i]);
    if (t < 128) { als[t] = al[t]; ars[t] = ar[t]; }

    int row0 = blockIdx.x * GR;
    for (int i = t; i < GR * 32; i += GEMM_THREADS) {
        int r = i >> 5, c4 = i & 31;
        int node = row0 + r;
        float4 h4 = make_float4(0.f, 0.f, 0.f, 0.f);
        if (node < nrows) {
            h4 = X ? ((const float4*)(X + (size_t)node * 128))[c4]
                   : ((const float4*)(g_h + (size_t)node * 128))[c4];
            h4 = tf32r4(h4);
        }
        ((float4*)Hs)[i] = h4;
    }
    __syncthreads();

    int tx = t & 31;          // col group: cols tx*4 .. tx*4+3 (all in head tx>>3)
    int ty = t >> 5;          // row group: rows ty*4 .. ty*4+3 (uniform per warp)
    float acc[4][4];
#pragma unroll
    for (int r = 0; r < 4; r++)
#pragma unroll
        for (int c = 0; c < 4; c++) acc[r][c] = 0.f;

#pragma unroll 4
    for (int kk = 0; kk < 128; kk += 4) {
        float4 wv[4], hv[4];
#pragma unroll
        for (int q = 0; q < 4; q++)
            wv[q] = *(const float4*)&Ws[(kk + q) * 128 + tx * 4];   // conflict-free
#pragma unroll
        for (int r = 0; r < 4; r++)
            hv[r] = *(const float4*)&Hs[(ty * 4 + r) * 128 + kk];   // warp broadcast
#pragma unroll
        for (int r = 0; r < 4; r++) {
            const float* h = (const float*)&hv[r];
#pragma unroll
            for (int c = 0; c < 4; c++) {
                const float* w0 = (const float*)&wv[0];
                const float* w1 = (const float*)&wv[1];
                const float* w2 = (const float*)&wv[2];
                const float* w3 = (const float*)&wv[3];
                acc[r][c] += h[0] * w0[c] + h[1] * w1[c] + h[2] * w2[c] + h[3] * w3[c];
            }
        }
    }

    int j0 = tx * 4;
    int head = tx >> 3;             // j0/32
    int d0 = (tx & 7) * 4;          // j0%32
    float a0 = als[j0], a1 = als[j0 + 1], a2 = als[j0 + 2], a3 = als[j0 + 3];
    float b0 = ars[j0], b1 = ars[j0 + 1], b2 = ars[j0 + 2], b3 = ars[j0 + 3];
#pragma unroll
    for (int r = 0; r < 4; r++) {
        int node = row0 + ty * 4 + r;
        float pa = acc[r][0] * a0 + acc[r][1] * a1 + acc[r][2] * a2 + acc[r][3] * a3;
        float pb = acc[r][0] * b0 + acc[r][1] * b1 + acc[r][2] * b2 + acc[r][3] * b3;
#pragma unroll
        for (int s = 4; s > 0; s >>= 1) {       // reduce over 8-lane head group
            pa += __shfl_xor_sync(0xffffffffu, pa, s);
            pb += __shfl_xor_sync(0xffffffffu, pb, s);
        }
        if (node < nrows) {
            float* frow = Fout + (size_t)node * 128;
            // head-interleaved store: col j -> offset (j%32)*4 + head
            frow[(d0 + 0) * 4 + head] = acc[r][0];
            frow[(d0 + 1) * 4 + head] = acc[r][1];
            frow[(d0 + 2) * 4 + head] = acc[r][2];
            frow[(d0 + 3) * 4 + head] = acc[r][3];
            if ((tx & 7) == 0) {
                elOut[node * HEADS + head] = pa;
                erOut[node * HEADS + head] = pb;
            }
        }
    }
}

// ---------------- edge aggregation: one warp per dst node ----------------
// BRANCHLESS softmax without max-subtraction: attention logits here are bounded
// (|e| << 88), so exp cannot overflow; alpha = exp(e)/sum exp(e) is identical to
// the max-subtracted form. Per edge per head: FADD, FMUL, FMNMX (leaky), exp
// (FMUL+MUFU), FADD, FFMA — no branches, no m/scale bookkeeping.
// wid != null -> layer 0 (vocab tables gathered through word_ids).
__global__ void edge_agg_kernel(const int* __restrict__ wid) {
    int gw = (blockIdx.x * blockDim.x + threadIdx.x) >> 5;
    int lane = threadIdx.x & 31;
    if (gw >= N_NODES) return;
    int n = gw;

    const float* F   = wid ? g_V   : g_feat;
    const float* ELV = wid ? g_elv : g_el;
    const float* ERV = wid ? g_erv : g_er;

    int nr = wid ? __ldg(&wid[n]) : n;
    float4 er4 = *(const float4*)&ERV[nr * HEADS];
    float er[4] = {er4.x, er4.y, er4.z, er4.w};
    float den[4] = {0.f, 0.f, 0.f, 0.f};
    float acc[4] = {0.f, 0.f, 0.f, 0.f};

    int s = g_off[n], e = g_off[n + 1];

    float4 el_p = make_float4(0.f, 0.f, 0.f, 0.f);
    float4 fv_p = make_float4(0.f, 0.f, 0.f, 0.f);
    if (s < e) {
        int src = __ldg(&g_srcsorted[s]);
        int r = wid ? __ldg(&wid[src]) : src;
        el_p = *(const float4*)&ELV[r * HEADS];
        fv_p = __ldg((const float4*)(F + (size_t)r * FEAT) + lane);  // [h0,h1,h2,h3] for dim=lane
    }
    for (int i = s; i < e; i++) {
        float4 el4 = el_p;
        float4 fv4 = fv_p;
        if (i + 1 < e) {
            int src = __ldg(&g_srcsorted[i + 1]);
            int r = wid ? __ldg(&wid[src]) : src;
            el_p = *(const float4*)&ELV[r * HEADS];
            fv_p = __ldg((const float4*)(F + (size_t)r * FEAT) + lane);
        }
        float el[4] = {el4.x, el4.y, el4.z, el4.w};
        float fv[4] = {fv4.x, fv4.y, fv4.z, fv4.w};
#pragma unroll
        for (int h = 0; h < 4; h++) {
            float x = el[h] + er[h];
            x = fmaxf(x, NEG_SLOPE * x);       // leaky relu (slope<1)
            float p = __expf(x);               // bounded, no overflow
            den[h] += p;
            acc[h] += p * fv[h];
        }
    }
#pragma unroll
    for (int h = 0; h < 4; h++) {
        float o = acc[h] / (den[h] + 1e-10f);  // empty node -> 0, matches reference
        o = (o > 0.f) ? o : expm1f(o);         // elu
        g_h[(size_t)n * FEAT + h * 32 + lane] = o;   // standard layout for next gemm/pool
    }
}

// ---------------- per-graph max pool (node_graph_id sorted -> run-length local max) ----------------
#define POOL_CHUNK 128
__global__ void pool_kernel(const int* __restrict__ gid) {
    int f = threadIdx.x;   // 128 threads = feature dims
    int n0 = blockIdx.x * POOL_CHUNK;
    int n1 = n0 + POOL_CHUNK; if (n1 > N_NODES) n1 = N_NODES;
    int cur = -1;
    unsigned best = 0;
    for (int n = n0; n < n1; n++) {
        int g = gid[n];                               // broadcast load
        unsigned enc = fenc(g_h[(size_t)n * FEAT + f]);
        if (g != cur) {
            if (cur >= 0) atomicMax(&g_pool[cur * FEAT + f], best);
            cur = g; best = enc;
        } else {
            best = best > enc ? best : enc;
        }
    }
    if (cur >= 0) atomicMax(&g_pool[cur * FEAT + f], best);
}

// ---------------- readout: logits (TF32 dot, matching reference), BCE loss, sigmoid ----------------
__global__ void final_kernel(const float* __restrict__ y, const float* __restrict__ ow,
                             const float* __restrict__ ob, float* __restrict__ out) {
    int g = threadIdx.x;   // 64 threads
    float s = 0.f;
    for (int k = 0; k < FEAT; k++) {
        float v = fdec(g_pool[g * FEAT + k]);
        if (!isfinite(v)) v = 0.f;   // empty-graph guard (also covers first-call 0-init pool)
        s += tf32r(v) * tf32r(ow[k]);
    }
    float l = s + ob[0];
    out[1 + g] = 1.f / (1.f + expf(-l));
    float bce = fmaxf(l, 0.f) - l * y[g] + log1pf(expf(-fabsf(l)));
    __shared__ float sh[64];
    sh[g] = bce;
    __syncthreads();
    for (int st = 32; st > 0; st >>= 1) {
        if (g < st) sh[g] += sh[g + st];
        __syncthreads();
    }
    if (g == 0) out[0] = sh[0] / (float)N_GRAPHS;
}

// ---------------- cleanup: restore scratch state for the next invocation ----------------
// Runs LAST every call; every execution therefore starts with g_deg=g_cur=0 and
// g_pool armed. First-ever execution uses static zero-init (0 is a valid max
// identity for fenc-encoded values; empty-graph outputs are identical either way).
__global__ void cleanup_kernel() {
    int i = blockIdx.x * blockDim.x + threadIdx.x;
    if (i < N_NODES) { g_deg[i] = 0; g_cur[i] = 0; }
    if (i < N_GRAPHS * FEAT) g_pool[i] = ENC_NEG_INF;
}

extern "C" void kernel_launch(void* const* d_in, const int* in_sizes, int n_in,
                              void* d_out, int out_size) {
    const int*   word_ids   = (const int*)  d_in[0];
    const int*   edge_src   = (const int*)  d_in[1];
    const int*   edge_dst   = (const int*)  d_in[2];
    const int*   node_gid   = (const int*)  d_in[3];
    const float* y_data     = (const float*)d_in[4];
    const float* word_emb   = (const float*)d_in[5];
    const float* W0         = (const float*)d_in[6];
    const float* al0        = (const float*)d_in[7];
    const float* ar0        = (const float*)d_in[8];
    const float* W1         = (const float*)d_in[9];
    const float* al1        = (const float*)d_in[10];
    const float* ar1        = (const float*)d_in[11];
    const float* out_w      = (const float*)d_in[12];
    const float* out_b      = (const float*)d_in[13];
    float* out = (float*)d_out;

    static float *pV = nullptr, *pElv, *pErv, *pFeat, *pEl, *pEr;
    if (!pV) {   // resolved once; pure address lookup, deterministic, enqueues no work
        cudaGetSymbolAddress((void**)&pV,    g_V);
        cudaGetSymbolAddress((void**)&pElv,  g_elv);
        cudaGetSymbolAddress((void**)&pErv,  g_erv);
        cudaGetSymbolAddress((void**)&pFeat, g_feat);
        cudaGetSymbolAddress((void**)&pEl,   g_el);
        cudaGetSymbolAddress((void**)&pEr,   g_er);
        cudaFuncSetAttribute(gemm_kernel, cudaFuncAttributeMaxDynamicSharedMemorySize, GEMM_SMEM);
    }

    // CSR build (rebuilt each call; deterministic inputs)
    deg_kernel<<<(N_EDGES + 255) / 256, 256>>>(edge_dst);
    scan_kernel<<<1, 1024>>>();
    scatter_kernel<<<(N_EDGES + 255) / 256, 256>>>(edge_src, edge_dst);

    int agg_blocks = (N_NODES * 32 + 255) / 256;

    // layer 0: GEMM over distinct vocab rows only (15000 instead of 50000)
    gemm_kernel<<<(VOCAB + GR - 1) / GR, GEMM_THREADS, GEMM_SMEM>>>(
        word_emb, VOCAB, W0, al0, ar0, pV, pElv, pErv);
    edge_agg_kernel<<<agg_blocks, 256>>>(word_ids);

    // layer 1: full node GEMM reading g_h (X==null)
    gemm_kernel<<<(N_NODES + GR - 1) / GR, GEMM_THREADS, GEMM_SMEM>>>(
        nullptr, N_NODES, W1, al1, ar1, pFeat, pEl, pEr);
    edge_agg_kernel<<<agg_blocks, 256>>>(nullptr);

    // pooling + readout
    pool_kernel<<<(N_NODES + POOL_CHUNK - 1) / POOL_CHUNK, 128>>>(node_gid);
    final_kernel<<<1, 64>>>(y_data, out_w, out_b, out);

    // restore scratch for next invocation
    cleanup_kernel<<<(N_NODES + 255) / 256, 256>>>();
}

// round 9
// speedup vs baseline: 1.8770x; 1.1882x over previous
#include <cuda_runtime.h>
#include <cuda_bf16.h>
#include <math.h>
#include <stdint.h>

#define N_NODES 50000
#define N_EDGES 800000
#define VOCAB 15000
#define IN_FEATS 128
#define HIDDEN 32
#define HEADS 4
#define FEAT 128           // HEADS*HIDDEN
#define N_GRAPHS 64
#define NEG_SLOPE 0.2f

// ---------------- scratch (static device globals; no allocation) ----------------
// feat tables stored HEAD-INTERLEAVED: row[d*4 + h] = feat[h*32 + d]
__device__ __align__(16) float g_V[(size_t)VOCAB * FEAT];      // vocab-level layer-0 feat (interleaved)
__device__ __align__(16) float g_elv[VOCAB * HEADS];
__device__ __align__(16) float g_erv[VOCAB * HEADS];
__device__ __align__(16) float g_feat[(size_t)N_NODES * FEAT]; // layer-1 feat (interleaved)
__device__ __align__(16) float g_h[(size_t)N_NODES * FEAT];    // layer output (standard layout)
__device__ __align__(16) float g_el[N_NODES * HEADS];
__device__ __align__(16) float g_er[N_NODES * HEADS];
__device__ __align__(16) int   g_deg[N_NODES];                 // zeroed by cleanup (and static-init)
__device__ __align__(16) int   g_cur[N_NODES];                 // zeroed by cleanup (and static-init)
__device__ __align__(16) int   g_off[N_NODES + 4];
__device__ __align__(16) int   g_srcsorted[N_EDGES];
__device__ unsigned g_pool[N_GRAPHS * FEAT];                   // re-armed by cleanup; 0 also a valid identity

// TF32 rounding (matches JAX/XLA default f32 matmul precision on GPU)
__device__ __forceinline__ float tf32r(float x) {
    unsigned u;
    asm("cvt.rna.tf32.f32 %0, %1;" : "=r"(u) : "f"(x));
    return __uint_as_float(u);
}
// exact split: bf16_hi + bf16_lo == tf32(x) (tf32: 11 sig bits; residual <=4 bits, bf16-exact)
__device__ __forceinline__ void split_bf(float x, __nv_bfloat16& h, __nv_bfloat16& l) {
    float xt = tf32r(x);
    h = __float2bfloat16(xt);
    l = __float2bfloat16(xt - __bfloat162float(h));
}

// order-preserving float <-> uint encode for atomicMax
__device__ __forceinline__ unsigned fenc(float f) {
    unsigned u = __float_as_uint(f);
    return (u & 0x80000000u) ? ~u : (u | 0x80000000u);
}
__device__ __forceinline__ float fdec(unsigned k) {
    return (k & 0x80000000u) ? __uint_as_float(k ^ 0x80000000u) : __uint_as_float(~k);
}
#define ENC_NEG_INF 0x007FFFFFu   // fenc(-inf)

// ---------------- CSR build ----------------
__global__ void deg_kernel(const int* __restrict__ dst) {
    int i = blockIdx.x * blockDim.x + threadIdx.x;
    if (i < N_EDGES) atomicAdd(&g_deg[dst[i]], 1);
}

__global__ void scan_kernel() {
    __shared__ int warp_base[32];
    __shared__ int carry_s;
    int t = threadIdx.x;
    int lane = t & 31, w = t >> 5;
    if (t == 0) carry_s = 0;
    __syncthreads();

    for (int base = 0; base < N_NODES; base += 4096) {
        int idx = base + t * 4;
        int4 v = make_int4(0, 0, 0, 0);
        if (idx + 3 < N_NODES) v = *(const int4*)&g_deg[idx];
        else {
            if (idx     < N_NODES) v.x = g_deg[idx];
            if (idx + 1 < N_NODES) v.y = g_deg[idx + 1];
            if (idx + 2 < N_NODES) v.z = g_deg[idx + 2];
        }
        int tsum = v.x + v.y + v.z + v.w;
        int sc = tsum;
#pragma unroll
        for (int d = 1; d < 32; d <<= 1) {
            int o = __shfl_up_sync(0xffffffffu, sc, d);
            if (lane >= d) sc += o;
        }
        if (lane == 31) warp_base[w] = sc;
        __syncthreads();
        if (w == 0) {
            int ws = warp_base[lane];
            int s2 = ws;
#pragma unroll
            for (int d = 1; d < 32; d <<= 1) {
                int o = __shfl_up_sync(0xffffffffu, s2, d);
                if (lane >= d) s2 += o;
            }
            warp_base[lane] = s2 - ws;
        }
        __syncthreads();
        int excl = carry_s + warp_base[w] + (sc - tsum);
        int4 o;
        o.x = excl; o.y = excl + v.x; o.z = o.y + v.y; o.w = o.z + v.z;
        if (idx + 3 < N_NODES) *(int4*)&g_off[idx] = o;
        else {
            if (idx     < N_NODES) g_off[idx]     = o.x;
            if (idx + 1 < N_NODES) g_off[idx + 1] = o.y;
            if (idx + 2 < N_NODES) g_off[idx + 2] = o.z;
        }
        __syncthreads();
        if (t == 1023) carry_s = excl + tsum;
        __syncthreads();
    }
    if (t == 0) g_off[N_NODES] = carry_s;
}

__global__ void scatter_kernel(const int* __restrict__ src, const int* __restrict__ dst) {
    int i = blockIdx.x * blockDim.x + threadIdx.x;
    if (i < N_EDGES) {
        int d = dst[i];
        int pos = g_off[d] + atomicAdd(&g_cur[d], 1);
        g_srcsorted[pos] = src[i];
    }
}

// ---------------- tensor-core GEMM (mma.sync bf16) + el/er ----------------
// Fout = tf32(X) @ tf32(W) via bf16 hi/lo split: AhBh + AlBh + AhBl (AlBl ~2^-16, dropped).
// As/Bs: [row][ hi(128) | lo(128) ] bf16, row pad 264. 24 k16-steps with base remap.
// 8 warps = 4 m-warps x 2 n-warps; each warp: 2 m-tiles(16) x 8 n-tiles(8), m16n8k16.
#define KP 264
#define TC_A_OFF   0
#define TC_B_OFF   (128 * KP * 2)                  // 67584
#define TC_EXTRA   (2 * 128 * KP * 2)              // 135168
#define TC_SEL_OFF (TC_EXTRA)                      // sEl [128][2]
#define TC_SER_OFF (TC_EXTRA + 1024)               // sEr [128][2]
#define TC_AL_OFF  (TC_EXTRA + 2048)               // als [128]
#define TC_AR_OFF  (TC_EXTRA + 2560)               // ars [128]
#define TC_SMEM    (TC_EXTRA + 3072)               // 138240 bytes

__global__ __launch_bounds__(256, 1) void gemm_tc_kernel(
    const float* __restrict__ X, int nrows, const float* __restrict__ W,
    const float* __restrict__ al, const float* __restrict__ ar,
    float* __restrict__ Fout, float* __restrict__ elOut, float* __restrict__ erOut)
{
    extern __shared__ char smem[];
    __nv_bfloat16* As = (__nv_bfloat16*)(smem + TC_A_OFF);
    __nv_bfloat16* Bs = (__nv_bfloat16*)(smem + TC_B_OFF);
    float* sEl = (float*)(smem + TC_SEL_OFF);
    float* sEr = (float*)(smem + TC_SER_OFF);
    float* als = (float*)(smem + TC_AL_OFF);
    float* ars = (float*)(smem + TC_AR_OFF);
    float* Ds  = (float*)(smem + TC_A_OFF);        // overlays As/Bs after MMA

    int t = threadIdx.x, wid = t >> 5, lane = t & 31;
    int g = lane >> 2, tq = lane & 3;
    int wm = wid >> 1, wn = wid & 1;
    int row0 = blockIdx.x * 128;

    if (t < 128) { als[t] = al[t]; ars[t] = ar[t]; }

    // ---- load A rows (hi/lo split): 2 threads per row ----
    {
        int r = t >> 1, kh = t & 1;
        bool valid = (row0 + r) < nrows;
        const float* xr = X ? (X + (size_t)(row0 + r) * 128) : (g_h + (size_t)(row0 + r) * 128);
        __nv_bfloat16* ah = As + r * KP + kh * 64;
        __nv_bfloat16* av = ah + 128;
#pragma unroll
        for (int f = 0; f < 16; f++) {
            float4 v = make_float4(0.f, 0.f, 0.f, 0.f);
            if (valid) v = ((const float4*)xr)[kh * 16 + f];
            __nv_bfloat16 h0, h1, h2, h3, l0, l1, l2, l3;
            split_bf(v.x, h0, l0); split_bf(v.y, h1, l1);
            split_bf(v.z, h2, l2); split_bf(v.w, h3, l3);
            ((__nv_bfloat162*)(ah + f * 4))[0] = __halves2bfloat162(h0, h1);
            ((__nv_bfloat162*)(ah + f * 4))[1] = __halves2bfloat162(h2, h3);
            ((__nv_bfloat162*)(av + f * 4))[0] = __halves2bfloat162(l0, l1);
            ((__nv_bfloat162*)(av + f * 4))[1] = __halves2bfloat162(l2, l3);
        }
    }
    // ---- load B = W^T (hi/lo): Bs[n][k]; 2 threads per W row k ----
    {
        int k = t >> 1, nh = t & 1;
#pragma unroll 4
        for (int j = 0; j < 16; j++) {
            float4 v = ((const float4*)(W + (size_t)k * 128 + nh * 64))[j];
            float vv[4] = {v.x, v.y, v.z, v.w};
#pragma unroll
            for (int e = 0; e < 4; e++) {
                int n = nh * 64 + j * 4 + e;
                __nv_bfloat16 hh, ll;
                split_bf(vv[e], hh, ll);
                Bs[n * KP + k]       = hh;
                Bs[n * KP + 128 + k] = ll;
            }
        }
    }
    __syncthreads();

    // ---- 24 k-steps: s<8 AhBh, 8..15 AlBh, 16..23 AhBl ----
    float acc[2][8][4];
#pragma unroll
    for (int mt = 0; mt < 2; mt++)
#pragma unroll
        for (int nt = 0; nt < 8; nt++)
#pragma unroll
            for (int c = 0; c < 4; c++) acc[mt][nt][c] = 0.f;

#pragma unroll
    for (int s = 0; s < 24; s++) {
        int abase = (s < 8) ? s * 16 : (s < 16) ? 128 + (s - 8) * 16 : (s - 16) * 16;
        int bbase = (s < 8) ? s * 16 : (s < 16) ? (s - 8) * 16 : 128 + (s - 16) * 16;
        uint32_t af[2][4], bf[8][2];
#pragma unroll
        for (int mt = 0; mt < 2; mt++) {
            int r = wm * 32 + mt * 16 + g;
            af[mt][0] = *(const uint32_t*)&As[r * KP + abase + 2 * tq];
            af[mt][1] = *(const uint32_t*)&As[(r + 8) * KP + abase + 2 * tq];
            af[mt][2] = *(const uint32_t*)&As[r * KP + abase + 2 * tq + 8];
            af[mt][3] = *(const uint32_t*)&As[(r + 8) * KP + abase + 2 * tq + 8];
        }
#pragma unroll
        for (int nt = 0; nt < 8; nt++) {
            int n = wn * 64 + nt * 8 + g;
            bf[nt][0] = *(const uint32_t*)&Bs[n * KP + bbase + 2 * tq];
            bf[nt][1] = *(const uint32_t*)&Bs[n * KP + bbase + 2 * tq + 8];
        }
#pragma unroll
        for (int mt = 0; mt < 2; mt++)
#pragma unroll
            for (int nt = 0; nt < 8; nt++)
                asm volatile(
                    "mma.sync.aligned.m16n8k16.row.col.f32.bf16.bf16.f32 "
                    "{%0,%1,%2,%3}, {%4,%5,%6,%7}, {%8,%9}, {%0,%1,%2,%3};"
                    : "+f"(acc[mt][nt][0]), "+f"(acc[mt][nt][1]),
                      "+f"(acc[mt][nt][2]), "+f"(acc[mt][nt][3])
                    : "r"(af[mt][0]), "r"(af[mt][1]), "r"(af[mt][2]), "r"(af[mt][3]),
                      "r"(bf[nt][0]), "r"(bf[nt][1]));
    }

    // ---- el/er partials from register fragments ----
    float pa[2][2] = {{0.f, 0.f}, {0.f, 0.f}};   // [mt][row-low/high]
    float pb[2][2] = {{0.f, 0.f}, {0.f, 0.f}};
#pragma unroll
    for (int mt = 0; mt < 2; mt++)
#pragma unroll
        for (int nt = 0; nt < 8; nt++) {
            int c = wn * 64 + nt * 8 + 2 * tq;
            float a0 = als[c], a1 = als[c + 1];
            float b0 = ars[c], b1 = ars[c + 1];
            pa[mt][0] += acc[mt][nt][0] * a0 + acc[mt][nt][1] * a1;
            pa[mt][1] += acc[mt][nt][2] * a0 + acc[mt][nt][3] * a1;
            pb[mt][0] += acc[mt][nt][0] * b0 + acc[mt][nt][1] * b1;
            pb[mt][1] += acc[mt][nt][2] * b0 + acc[mt][nt][3] * b1;
        }
#pragma unroll
    for (int mt = 0; mt < 2; mt++)
#pragma unroll
        for (int q = 0; q < 2; q++) {
            pa[mt][q] += __shfl_xor_sync(0xffffffffu, pa[mt][q], 1);
            pa[mt][q] += __shfl_xor_sync(0xffffffffu, pa[mt][q], 2);
            pb[mt][q] += __shfl_xor_sync(0xffffffffu, pb[mt][q], 1);
            pb[mt][q] += __shfl_xor_sync(0xffffffffu, pb[mt][q], 2);
        }
    if (tq == 0) {
#pragma unroll
        for (int mt = 0; mt < 2; mt++) {
            int r = wm * 32 + mt * 16 + g;
            sEl[r * 2 + wn] = pa[mt][0];       sEr[r * 2 + wn] = pb[mt][0];
            sEl[(r + 8) * 2 + wn] = pa[mt][1]; sEr[(r + 8) * 2 + wn] = pb[mt][1];
        }
    }
    __syncthreads();   // all warps done with As/Bs and sEl/sEr writes

    // ---- stage C to Ds[128][132] (overlays As/Bs) ----
#pragma unroll
    for (int mt = 0; mt < 2; mt++)
#pragma unroll
        for (int nt = 0; nt < 8; nt++) {
            int r = wm * 32 + mt * 16 + g;
            int c = wn * 64 + nt * 8 + 2 * tq;
            *(float2*)&Ds[r * 132 + c]       = make_float2(acc[mt][nt][0], acc[mt][nt][1]);
            *(float2*)&Ds[(r + 8) * 132 + c] = make_float2(acc[mt][nt][2], acc[mt][nt][3]);
        }
    // el/er writeback (independent of Ds)
    if (t < 128) {
        int node = row0 + t;
        if (node < nrows) {
#pragma unroll
            for (int h = 0; h < 1; h++) {}     // keep structure simple
            // el/er stored per head: rows of sEl are full 128-dim; heads are col ranges.
        }
    }
    __syncthreads();

    // el/er: sEl[r][0]+sEl[r][1] is the dot over all 128 cols... but el is PER-HEAD.
    // Head h covers cols [h*32, h*32+32). Cols were split by wn (0..63 | 64..127), i.e.
    // heads 0,1 in wn=0 and heads 2,3 in wn=1 — but partials were summed across nt
    // WITHIN wn, mixing two heads. So recompute el/er from Ds instead (cheap, correct):
    if (wid < 4) {
        int rr = wid * 32 + lane;
        int node = row0 + rr;
        if (node < nrows) {
#pragma unroll
            for (int h = 0; h < 4; h++) {
                float sa = 0.f, sb = 0.f;
#pragma unroll
                for (int d = 0; d < 32; d++) {
                    float fv = Ds[rr * 132 + h * 32 + d];
                    sa += fv * als[h * 32 + d];
                    sb += fv * ars[h * 32 + d];
                }
                elOut[node * HEADS + h] = sa;
                erOut[node * HEADS + h] = sb;
            }
        }
    }

    // ---- feat writeback: head-interleaved float4 rows, coalesced ----
#pragma unroll 4
    for (int it = 0; it < 16; it++) {
        int rr = wid * 16 + it;
        int node = row0 + rr;
        if (node < nrows) {
            float4 o;
            o.x = Ds[rr * 132 +      lane];
            o.y = Ds[rr * 132 + 32 + lane];
            o.z = Ds[rr * 132 + 64 + lane];
            o.w = Ds[rr * 132 + 96 + lane];
            ((float4*)(Fout + (size_t)node * 128))[lane] = o;   // frow[d*4+h]
        }
    }
}

// ---------------- edge aggregation: one warp per dst node, branchless softmax ----------------
__global__ void edge_agg_kernel(const int* __restrict__ wid) {
    int gw = (blockIdx.x * blockDim.x + threadIdx.x) >> 5;
    int lane = threadIdx.x & 31;
    if (gw >= N_NODES) return;
    int n = gw;

    const float* F   = wid ? g_V   : g_feat;
    const float* ELV = wid ? g_elv : g_el;
    const float* ERV = wid ? g_erv : g_er;

    int nr = wid ? __ldg(&wid[n]) : n;
    float4 er4 = *(const float4*)&ERV[nr * HEADS];
    float er[4] = {er4.x, er4.y, er4.z, er4.w};
    float den[4] = {0.f, 0.f, 0.f, 0.f};
    float acc[4] = {0.f, 0.f, 0.f, 0.f};

    int s = g_off[n], e = g_off[n + 1];

    float4 el_p = make_float4(0.f, 0.f, 0.f, 0.f);
    float4 fv_p = make_float4(0.f, 0.f, 0.f, 0.f);
    if (s < e) {
        int src = __ldg(&g_srcsorted[s]);
        int r = wid ? __ldg(&wid[src]) : src;
        el_p = *(const float4*)&ELV[r * HEADS];
        fv_p = __ldg((const float4*)(F + (size_t)r * FEAT) + lane);
    }
    for (int i = s; i < e; i++) {
        float4 el4 = el_p;
        float4 fv4 = fv_p;
        if (i + 1 < e) {
            int src = __ldg(&g_srcsorted[i + 1]);
            int r = wid ? __ldg(&wid[src]) : src;
            el_p = *(const float4*)&ELV[r * HEADS];
            fv_p = __ldg((const float4*)(F + (size_t)r * FEAT) + lane);
        }
        float el[4] = {el4.x, el4.y, el4.z, el4.w};
        float fv[4] = {fv4.x, fv4.y, fv4.z, fv4.w};
#pragma unroll
        for (int h = 0; h < 4; h++) {
            float x = el[h] + er[h];
            x = fmaxf(x, NEG_SLOPE * x);       // leaky relu (slope<1)
            float p = __expf(x);               // bounded logits, no overflow
            den[h] += p;
            acc[h] += p * fv[h];
        }
    }
#pragma unroll
    for (int h = 0; h < 4; h++) {
        float o = acc[h] / (den[h] + 1e-10f);
        o = (o > 0.f) ? o : expm1f(o);         // elu
        g_h[(size_t)n * FEAT + h * 32 + lane] = o;
    }
}

// ---------------- per-graph max pool ----------------
#define POOL_CHUNK 128
__global__ void pool_kernel(const int* __restrict__ gid) {
    int f = threadIdx.x;
    int n0 = blockIdx.x * POOL_CHUNK;
    int n1 = n0 + POOL_CHUNK; if (n1 > N_NODES) n1 = N_NODES;
    int cur = -1;
    unsigned best = 0;
    for (int n = n0; n < n1; n++) {
        int g = gid[n];
        unsigned enc = fenc(g_h[(size_t)n * FEAT + f]);
        if (g != cur) {
            if (cur >= 0) atomicMax(&g_pool[cur * FEAT + f], best);
            cur = g; best = enc;
        } else {
            best = best > enc ? best : enc;
        }
    }
    if (cur >= 0) atomicMax(&g_pool[cur * FEAT + f], best);
}

// ---------------- readout ----------------
__global__ void final_kernel(const float* __restrict__ y, const float* __restrict__ ow,
                             const float* __restrict__ ob, float* __restrict__ out) {
    int g = threadIdx.x;   // 64 threads
    float s = 0.f;
    for (int k = 0; k < FEAT; k++) {
        float v = fdec(g_pool[g * FEAT + k]);
        if (!isfinite(v)) v = 0.f;
        s += tf32r(v) * tf32r(ow[k]);
    }
    float l = s + ob[0];
    out[1 + g] = 1.f / (1.f + expf(-l));
    float bce = fmaxf(l, 0.f) - l * y[g] + log1pf(expf(-fabsf(l)));
    __shared__ float sh[64];
    sh[g] = bce;
    __syncthreads();
    for (int st = 32; st > 0; st >>= 1) {
        if (g < st) sh[g] += sh[g + st];
        __syncthreads();
    }
    if (g == 0) out[0] = sh[0] / (float)N_GRAPHS;
}

// ---------------- cleanup: restore scratch for next invocation ----------------
__global__ void cleanup_kernel() {
    int i = blockIdx.x * blockDim.x + threadIdx.x;
    if (i < N_NODES) { g_deg[i] = 0; g_cur[i] = 0; }
    if (i < N_GRAPHS * FEAT) g_pool[i] = ENC_NEG_INF;
}

extern "C" void kernel_launch(void* const* d_in, const int* in_sizes, int n_in,
                              void* d_out, int out_size) {
    const int*   word_ids   = (const int*)  d_in[0];
    const int*   edge_src   = (const int*)  d_in[1];
    const int*   edge_dst   = (const int*)  d_in[2];
    const int*   node_gid   = (const int*)  d_in[3];
    const float* y_data     = (const float*)d_in[4];
    const float* word_emb   = (const float*)d_in[5];
    const float* W0         = (const float*)d_in[6];
    const float* al0        = (const float*)d_in[7];
    const float* ar0        = (const float*)d_in[8];
    const float* W1         = (const float*)d_in[9];
    const float* al1        = (const float*)d_in[10];
    const float* ar1        = (const float*)d_in[11];
    const float* out_w      = (const float*)d_in[12];
    const float* out_b      = (const float*)d_in[13];
    float* out = (float*)d_out;

    static float *pV = nullptr, *pElv, *pErv, *pFeat, *pEl, *pEr;
    if (!pV) {   // resolved once; pure address lookup, enqueues no work
        cudaGetSymbolAddress((void**)&pV,    g_V);
        cudaGetSymbolAddress((void**)&pElv,  g_elv);
        cudaGetSymbolAddress((void**)&pErv,  g_erv);
        cudaGetSymbolAddress((void**)&pFeat, g_feat);
        cudaGetSymbolAddress((void**)&pEl,   g_el);
        cudaGetSymbolAddress((void**)&pEr,   g_er);
        cudaFuncSetAttribute(gemm_tc_kernel, cudaFuncAttributeMaxDynamicSharedMemorySize, TC_SMEM);
    }

    // CSR build (rebuilt each call; deterministic inputs)
    deg_kernel<<<(N_EDGES + 255) / 256, 256>>>(edge_dst);
    scan_kernel<<<1, 1024>>>();
    scatter_kernel<<<(N_EDGES + 255) / 256, 256>>>(edge_src, edge_dst);

    int agg_blocks = (N_NODES * 32 + 255) / 256;

    // layer 0: tensor-core GEMM over distinct vocab rows (15000)
    gemm_tc_kernel<<<(VOCAB + 127) / 128, 256, TC_SMEM>>>(
        word_emb, VOCAB, W0, al0, ar0, pV, pElv, pErv);
    edge_agg_kernel<<<agg_blocks, 256>>>(word_ids);

    // layer 1: tensor-core GEMM over all nodes (X==null -> reads g_h)
    gemm_tc_kernel<<<(N_NODES + 127) / 128, 256, TC_SMEM>>>(
        nullptr, N_NODES, W1, al1, ar1, pFeat, pEl, pEr);
    edge_agg_kernel<<<agg_blocks, 256>>>(nullptr);

    // pooling + readout
    pool_kernel<<<(N_NODES + POOL_CHUNK - 1) / POOL_CHUNK, 128>>>(node_gid);
    final_kernel<<<1, 64>>>(y_data, out_w, out_b, out);

    // restore scratch for next invocation
    cleanup_kernel<<<(N_NODES + 255) / 256, 256>>>();
}